// round 5
// baseline (speedup 1.0000x reference)
#include <cuda_runtime.h>
#include <math.h>

#define Tn 1024
#define Bn 512
#define CH 64
#define NCH 16
#define Hn 20
#define NB 128
#define OUT_DIFF (Tn * Bn * 3)

// ---------------- serial B chunk: warp-systolic, branch-free, per-step owner stores ----------------
template <int FIRST>
__device__ __forceinline__ void serialChunk(int k, int bb, int wid, int lane,
                                            float& S, float& I, float& R,
                                            float acc0, float acc1,
                                            float dtv, float beta, float gamma,
                                            const float* __restrict__ cwS,
                                            float (*Ih)[Tn],
                                            float* __restrict__ out) {
    if (FIRST) {
        acc0 = cwS[32 + lane] * I;           // I_0 contribution (cw[0]=0 pads lane 0)
        acc1 = cwS[64 + lane] * I;
    }
    float* diffb = out + OUT_DIFF;

#pragma unroll
    for (int s = FIRST ? 1 : 0; s < 32; s++) {
        float integro = __shfl_sync(0xffffffffu, acc0, s);
        float bSI = beta * S * I;
        float dS = integro - bSI;
        float dI = bSI - gamma * I;
        float dR = gamma * I - integro;
        S = fmaf(dtv, dS, S); I = fmaf(dtv, dI, I); R = fmaf(dtv, dR, R);
        if (lane == s) {                      // predicated owner stores, off latency chain
            int j = k * CH + s;
            float* so = out + ((size_t)j * Bn + bb) * 3;
            so[0] = S; so[1] = I; so[2] = R;
            float* df = diffb + ((size_t)(j - 1) * Bn + bb) * 3;
            df[0] = dS; df[1] = dI; df[2] = dR;
            Ih[wid][j] = I;
        }
        acc0 = fmaf(cwS[32 + lane - s], I, acc0);   // d = lane-s (zero pad for lane<=s)
        acc1 = fmaf(cwS[64 + lane - s], I, acc1);   // d = lane+32-s
    }
#pragma unroll
    for (int s2 = 0; s2 < 32; s2++) {
        float integro = __shfl_sync(0xffffffffu, acc1, s2);
        float bSI = beta * S * I;
        float dS = integro - bSI;
        float dI = bSI - gamma * I;
        float dR = gamma * I - integro;
        S = fmaf(dtv, dS, S); I = fmaf(dtv, dI, I); R = fmaf(dtv, dR, R);
        if (lane == s2) {
            int j = k * CH + 32 + s2;
            float* so = out + ((size_t)j * Bn + bb) * 3;
            so[0] = S; so[1] = I; so[2] = R;
            float* df = diffb + ((size_t)(j - 1) * Bn + bb) * 3;
            df[0] = dS; df[1] = dI; df[2] = dR;
            Ih[wid][j] = I;
        }
        acc1 = fmaf(cwS[32 + lane - s2], I, acc1);  // d = (lane+32)-(s2+32)
    }
}

// ---------------- the single block-local persistent kernel ----------------
__global__ void __launch_bounds__(256, 1)
mega(const float* __restrict__ t,  const float* __restrict__ y,
     const float* __restrict__ w1, const float* __restrict__ b1,
     const float* __restrict__ w2, const float* __restrict__ b2,
     const float* __restrict__ w3, const float* __restrict__ b3,
     const float* __restrict__ w4, const float* __restrict__ b4,
     const float* __restrict__ beta_p, const float* __restrict__ gamma_p,
     float* __restrict__ out) {
    __shared__ float cwS[1056];            // [0..32]=0; cwS[32+d]=cw[d]=me[Tn-d]*dt
    __shared__ float Ih[4][Tn];            // block-local I history per batch (16 KB)
    __shared__ float baseS[2][4][CH];      // A partials, double-buffered by target-chunk parity
    __shared__ float sw2[Hn * Hn], sw3[Hn * Hn];
    __shared__ float sw1[Hn], sb1[Hn], sb2[Hn], sb3[Hn], sw4[Hn];

    const int tid  = threadIdx.x;
    const int blk  = blockIdx.x;
    const int wid  = tid >> 5;
    const int lane = tid & 31;
    const int bj   = wid & 3;              // batch slot within block
    const int bb   = blk * 4 + bj;         // global batch

    const float dtv   = t[0] - t[1];
    const float beta  = beta_p[0];
    const float gamma = gamma_p[0];

    // ---- load MLP weights to smem; zero cw pad ----
    for (int i = tid; i < Hn * Hn; i += 256) { sw2[i] = w2[i]; sw3[i] = w3[i]; }
    if (tid < Hn) {
        sw1[tid] = w1[tid]; sb1[tid] = b1[tid];
        sb2[tid] = b2[tid]; sb3[tid] = b3[tid];
        sw4[tid] = w4[tid];
    }
    if (tid < 33) cwS[tid] = 0.0f;         // pad [0..31] + cw[0]=0
    __syncthreads();

    // ---- MLP: every block computes all 1024 me values (redundant, barrier-free) ----
#pragma unroll
    for (int q = 0; q < 4; q++) {
        int r = (q << 8) + tid;            // 0..1023
        float tv = t[r];
        float h1[Hn], h2[Hn];
#pragma unroll
        for (int j = 0; j < Hn; j++) h1[j] = tanhf(tv * sw1[j] + sb1[j]);
#pragma unroll
        for (int j = 0; j < Hn; j++) {
            float a = sb2[j];
#pragma unroll
            for (int i = 0; i < Hn; i++) a += h1[i] * sw2[i * Hn + j];
            h2[j] = tanhf(a);
        }
#pragma unroll
        for (int j = 0; j < Hn; j++) {
            float a = sb3[j];
#pragma unroll
            for (int i = 0; i < Hn; i++) a += h2[i] * sw3[i * Hn + j];
            h1[j] = tanhf(a);              // h3
        }
        float a = b4[0];
#pragma unroll
        for (int i = 0; i < Hn; i++) a += h1[i] * sw4[i];
        float me = 1.0f / (1.0f + expf(-a));
        if (r > 0) cwS[32 + Tn - r] = me * dtv;   // indices 33..1055; me[0] unused
    }

    // ---- init: this block's 4 batches — row 0, diff row Tn-1, Ih[.][0] ----
    if (tid < 4) {
        int b0 = blk * 4 + tid;
        float S0 = y[b0 * 3 + 0], I0 = y[b0 * 3 + 1], R0 = y[b0 * 3 + 2];
        float* so = out + (size_t)b0 * 3;                  // row 0
        so[0] = S0; so[1] = I0; so[2] = R0;
        float* df = out + OUT_DIFF + ((size_t)(Tn - 1) * Bn + b0) * 3;
        df[0] = 0.0f; df[1] = 0.0f; df[2] = 0.0f;
        Ih[tid][0] = I0;
    }
    __syncthreads();

    // ---- persistent B state ----
    float S = 0.f, I = 0.f, R = 0.f;
    if (wid < 4) { S = y[bb * 3 + 0]; I = y[bb * 3 + 1]; R = y[bb * 3 + 2]; }

    // ================= chunk loop (block-local; __syncthreads only) =================
    for (int k = 0; k < NCH; k++) {
        if (wid < 4) {
            // ----- B role: serial chunk for batch bj -----
            float acc0 = 0.0f, acc1 = 0.0f;
            if (k >= 2) {                      // old-history partials from A (target chunk k)
                acc0 = baseS[k & 1][bj][lane];
                acc1 = baseS[k & 1][bj][lane + 32];
            }
            if (k >= 1) {                      // recent: previous chunk from smem history
                const float* Iprev = &Ih[bj][(k - 1) * CH];
                const float* c0 = &cwS[96 + lane];    // d = 64+lane-m in [1,95]
                const float* c1 = &cwS[128 + lane];   // d = 96+lane-m in [33,127]
#pragma unroll 8
                for (int m = 0; m < CH; m++) {
                    float Iv = Iprev[m];
                    acc0 = fmaf(c0[-m], Iv, acc0);
                    acc1 = fmaf(c1[-m], Iv, acc1);
                }
                serialChunk<0>(k, bb, bj, lane, S, I, R, acc0, acc1,
                               dtv, beta, gamma, cwS, Ih, out);
            } else {
                serialChunk<1>(k, bb, bj, lane, S, I, R, acc0, acc1,
                               dtv, beta, gamma, cwS, Ih, out);
            }
        } else if (k >= 1 && k <= NCH - 2) {
            // ----- A role: old-history partials for target chunk K=k+1, batch bj -----
            const int K = k + 1;
            const int M = CH * k;              // m < 64k
            const float* Ihp = Ih[bj];
            const float* c0p = &cwS[32 + CH * K + lane];  // d = 64K+lane-m
            const float* c1p = c0p + 32;
            float acc0 = 0.0f, acc1 = 0.0f;
#pragma unroll 4
            for (int m = 0; m < M; m++) {
                float Iv = Ihp[m];             // broadcast LDS
                acc0 = fmaf(c0p[-m], Iv, acc0);
                acc1 = fmaf(c1p[-m], Iv, acc1);
            }
            baseS[K & 1][bj][lane]      = acc0;
            baseS[K & 1][bj][lane + 32] = acc1;
        }
        __syncthreads();                       // order baseS/Ih across roles for next chunk
    }
}

// ================= launch: ONE node, no barriers, no device globals =================
extern "C" void kernel_launch(void* const* d_in, const int* in_sizes, int n_in,
                              void* d_out, int out_size) {
    const float* t    = (const float*)d_in[0];
    const float* y    = (const float*)d_in[1];
    const float* w1   = (const float*)d_in[2];
    const float* b1   = (const float*)d_in[3];
    const float* w2   = (const float*)d_in[4];
    const float* b2   = (const float*)d_in[5];
    const float* w3   = (const float*)d_in[6];
    const float* b3   = (const float*)d_in[7];
    const float* w4   = (const float*)d_in[8];
    const float* b4   = (const float*)d_in[9];
    const float* beta = (const float*)d_in[10];
    const float* gamma= (const float*)d_in[11];
    float* out = (float*)d_out;

    mega<<<NB, 256>>>(t, y, w1, b1, w2, b2, w3, b3, w4, b4, beta, gamma, out);
}

// round 6
// speedup vs baseline: 2.1361x; 2.1361x over previous
#include <cuda_runtime.h>
#include <math.h>

#define Tn 1024
#define Bn 512
#define CH 64
#define NCH 16
#define Hn 20
#define NB 128
#define OUT_DIFF (Tn * Bn * 3)

__device__ float g_cw[1024];   // cw[d] = me[Tn-d]*dt for d in [1,1023]; cw[0]=0

// ============================================================
// k_init: MLP -> g_cw; solution row 0; diff row Tn-1 (zeros).
// ============================================================
__global__ void k_init(const float* __restrict__ t, const float* __restrict__ y,
                       const float* __restrict__ w1, const float* __restrict__ b1,
                       const float* __restrict__ w2, const float* __restrict__ b2,
                       const float* __restrict__ w3, const float* __restrict__ b3,
                       const float* __restrict__ w4, const float* __restrict__ b4,
                       float* __restrict__ out) {
    __shared__ float sw2[Hn * Hn], sw3[Hn * Hn];
    __shared__ float sw1[Hn], sb1[Hn], sb2[Hn], sb3[Hn], sw4[Hn];
    int tid = threadIdx.x;
    for (int i = tid; i < Hn * Hn; i += 256) { sw2[i] = w2[i]; sw3[i] = w3[i]; }
    if (tid < Hn) {
        sw1[tid] = w1[tid]; sb1[tid] = b1[tid];
        sb2[tid] = b2[tid]; sb3[tid] = b3[tid]; sw4[tid] = w4[tid];
    }
    __syncthreads();

    int r = blockIdx.x * 256 + tid;          // 0..1023
    float dt = t[0] - t[1];
    float tv = t[r];

    float h1[Hn], h2[Hn];
#pragma unroll
    for (int j = 0; j < Hn; j++) h1[j] = tanhf(tv * sw1[j] + sb1[j]);
#pragma unroll
    for (int j = 0; j < Hn; j++) {
        float a = sb2[j];
#pragma unroll
        for (int i = 0; i < Hn; i++) a += h1[i] * sw2[i * Hn + j];
        h2[j] = tanhf(a);
    }
#pragma unroll
    for (int j = 0; j < Hn; j++) {
        float a = sb3[j];
#pragma unroll
        for (int i = 0; i < Hn; i++) a += h2[i] * sw3[i * Hn + j];
        h1[j] = tanhf(a);
    }
    float a = b4[0];
#pragma unroll
    for (int i = 0; i < Hn; i++) a += h1[i] * sw4[i];
    float me = 1.0f / (1.0f + expf(-a));

    if (r > 0) g_cw[Tn - r] = me * dt;
    else       g_cw[0] = 0.0f;

    if (r < Bn) {
        float S0 = y[r * 3 + 0], I0 = y[r * 3 + 1], R0 = y[r * 3 + 2];
        float* so = out + (size_t)r * 3;
        so[0] = S0; so[1] = I0; so[2] = R0;
        float* df = out + OUT_DIFF + ((size_t)(Tn - 1) * Bn + r) * 3;
        df[0] = 0.0f; df[1] = 0.0f; df[2] = 0.0f;
    }
}

// ============================================================
// mega: persistent block-local solver. 128 blocks x 256 thr.
// Warps 0-3: B (serial Euler, pipelined shfl). Warps 4-7: A (history conv).
// ============================================================
__global__ void __launch_bounds__(256, 1)
mega(const float* __restrict__ t, const float* __restrict__ y,
     const float* __restrict__ beta_p, const float* __restrict__ gamma_p,
     float* __restrict__ out) {
    __shared__ float cwZ[1056];        // cwZ[i]=0 for i<=36 (pad + d<=4 local window); else cw[i-32]
    __shared__ float Ih[4][Tn];        // block-local I history
    __shared__ float baseS[2][4][CH];  // A partials, parity double-buffered

    const int tid  = threadIdx.x;
    const int blk  = blockIdx.x;
    const int wid  = tid >> 5;
    const int lane = tid & 31;
    const int bj   = wid & 3;
    const int bb   = blk * 4 + bj;

    for (int i = tid; i < 1056; i += 256)
        cwZ[i] = (i <= 36) ? 0.0f : g_cw[i - 32];
    if (tid < 4) Ih[tid][0] = y[(blk * 4 + tid) * 3 + 1];
    __syncthreads();

    const float dtv   = t[0] - t[1];
    const float beta  = beta_p[0];
    const float gamma = gamma_p[0];
    // true local coefficients d=1..4 (zeroed in cwZ)
    const float cw1 = __ldg(&g_cw[1]), cw2 = __ldg(&g_cw[2]);
    const float cw3 = __ldg(&g_cw[3]), cw4 = __ldg(&g_cw[4]);

    // persistent B state
    float S = 0.f, I = 0.f, tot = 0.f;
    float Im1 = 0.f, Im2 = 0.f, Im3 = 0.f, Im4 = 0.f;
    if (wid < 4) {
        S = y[bb * 3 + 0]; I = y[bb * 3 + 1];
        tot = S + I + y[bb * 3 + 2];
        Im1 = I;                         // I_0 is the most recent production before step 1
    }
    float* const diffb = out + OUT_DIFF;

    for (int k = 0; k < NCH; k++) {
        if (wid < 4) {
            // ---------- seed accumulators ----------
            float acc0, acc1;
            if (k >= 2) { acc0 = baseS[k & 1][bj][lane]; acc1 = baseS[k & 1][bj][lane + 32]; }
            else        { acc0 = 0.f; acc1 = 0.f; }
            if (k >= 1) {
                const float* Iprev = &Ih[bj][(k - 1) * CH];
                const float* c0 = &cwZ[96 + lane];     // d=64+lane-m (d<=4 zeroed -> local)
                const float* c1 = &cwZ[128 + lane];    // d=96+lane-m
#pragma unroll 8
                for (int m = 0; m < CH; m++) {
                    float Iv = Iprev[m];
                    acc0 = fmaf(c0[-m], Iv, acc0);
                    acc1 = fmaf(c1[-m], Iv, acc1);
                }
            } else {
                acc0 = cwZ[32 + lane] * I;             // I_0 scatter, d=lane (d<=4 zeroed)
                acc1 = cwZ[64 + lane] * I;             // d=lane+32
            }

            float svS0 = 0.f, svI0 = 0.f, svdS0 = 0.f, svdI0 = 0.f;
            float svS1, svI1, svdS1, svdI1;
            float preQ[4], preQ2[4];

            // ---------- half 1: steps s0..31, extraction from acc0 ----------
            const int s0 = (k == 0) ? 1 : 0;
#pragma unroll
            for (int r = 0; r < 4; r++)
                preQ[(s0 + r) & 3] = __shfl_sync(0xffffffffu, acc0, s0 + r);

#pragma unroll
            for (int s = 0; s < 32; s++) {
                if (s < 1 && s < s0) continue;         // skip s=0 on first chunk
                float integro = preQ[s & 3];
                integro = fmaf(cw4, Im4, integro);
                integro = fmaf(cw3, Im3, integro);
                integro = fmaf(cw2, Im2, integro);
                integro = fmaf(cw1, Im1, integro);
                if (s + 4 < 32) preQ[(s + 4) & 3]   = __shfl_sync(0xffffffffu, acc0, s + 4);
                else            preQ2[(s - 28) & 3] = __shfl_sync(0xffffffffu, acc1, s - 28);
                float bSI = beta * S * I;
                float dS  = integro - bSI;
                float dI  = fmaf(-gamma, I, bSI);
                S = fmaf(dtv, dS, S);
                I = fmaf(dtv, dI, I);
                bool own = (lane == s);
                svS0  = own ? S  : svS0;  svI0  = own ? I  : svI0;
                svdS0 = own ? dS : svdS0; svdI0 = own ? dI : svdI0;
                acc0 = fmaf(cwZ[32 + lane - s], I, acc0);   // d=lane-s (<=4 zeroed)
                acc1 = fmaf(cwZ[64 + lane - s], I, acc1);   // d=lane+32-s
                Im4 = Im3; Im3 = Im2; Im2 = Im1; Im1 = I;
            }

            // ---------- half 2: steps 32..63, extraction from acc1 ----------
#pragma unroll
            for (int s2 = 0; s2 < 32; s2++) {
                float integro = preQ2[s2 & 3];
                integro = fmaf(cw4, Im4, integro);
                integro = fmaf(cw3, Im3, integro);
                integro = fmaf(cw2, Im2, integro);
                integro = fmaf(cw1, Im1, integro);
                if (s2 + 4 < 32) preQ2[(s2 + 4) & 3] = __shfl_sync(0xffffffffu, acc1, s2 + 4);
                float bSI = beta * S * I;
                float dS  = integro - bSI;
                float dI  = fmaf(-gamma, I, bSI);
                S = fmaf(dtv, dS, S);
                I = fmaf(dtv, dI, I);
                bool own = (lane == s2);
                svS1  = own ? S  : svS1;  svI1  = own ? I  : svI1;
                svdS1 = own ? dS : svdS1; svdI1 = own ? dI : svdI1;
                acc1 = fmaf(cwZ[32 + lane - s2], I, acc1);  // d=(lane+32)-(32+s2)
                Im4 = Im3; Im3 = Im2; Im2 = Im1; Im1 = I;
            }

            // ---------- end-of-chunk flush (off the serial path) ----------
            int j0 = k * CH + lane;
            if (!(k == 0 && lane == 0)) {
                float* so = out + ((size_t)j0 * Bn + bb) * 3;
                so[0] = svS0; so[1] = svI0; so[2] = tot - svS0 - svI0;
                float* df = diffb + ((size_t)(j0 - 1) * Bn + bb) * 3;
                df[0] = svdS0; df[1] = svdI0; df[2] = -svdS0 - svdI0;
                Ih[bj][j0] = svI0;
            }
            int j1 = j0 + 32;
            {
                float* so = out + ((size_t)j1 * Bn + bb) * 3;
                so[0] = svS1; so[1] = svI1; so[2] = tot - svS1 - svI1;
                float* df = diffb + ((size_t)(j1 - 1) * Bn + bb) * 3;
                df[0] = svdS1; df[1] = svdI1; df[2] = -svdS1 - svdI1;
                Ih[bj][j1] = svI1;
            }
        } else if (k >= 1 && k <= NCH - 2) {
            // ---------- A: history partials for chunk K=k+1, m < 64k ----------
            const int K   = k + 1;
            const int j8  = lane & 7;          // owns target steps 8*j8 .. 8*j8+7
            const int g   = lane >> 3;         // m-slice
            const int M   = CH * k;
            const int m0  = g * (M >> 2);
            const int m1  = m0 + (M >> 2);
            const int Cc  = 32 + CH * K + 8 * j8;
            const float* Ihp = Ih[bj];

            float acc[8];
#pragma unroll
            for (int r = 0; r < 8; r++) acc[r] = 0.0f;
            float q[8];                        // coef FIFO: q[r] = cwZ[Cc + r - m]
#pragma unroll
            for (int r = 0; r < 8; r++) q[r] = cwZ[Cc + r - m0];

#pragma unroll 8
            for (int m = m0; m < m1; m++) {
                float Iv = Ihp[m];
#pragma unroll
                for (int r = 0; r < 8; r++) acc[r] = fmaf(q[r], Iv, acc[r]);
                float nc = cwZ[Cc - 1 - m];    // coef for r=0 at m+1
#pragma unroll
                for (int r = 7; r >= 1; r--) q[r] = q[r - 1];
                q[0] = nc;
            }
            // reduce the 4 m-slices (groups differ in bit3/bit4 of lane)
#pragma unroll
            for (int r = 0; r < 8; r++) {
                acc[r] += __shfl_xor_sync(0xffffffffu, acc[r], 8);
                acc[r] += __shfl_xor_sync(0xffffffffu, acc[r], 16);
            }
            if (lane < 8) {
                float4* dst = (float4*)&baseS[K & 1][bj][8 * j8];
                dst[0] = make_float4(acc[0], acc[1], acc[2], acc[3]);
                dst[1] = make_float4(acc[4], acc[5], acc[6], acc[7]);
            }
        }
        __syncthreads();
    }
}

// ================= launch: 2 graph nodes =================
extern "C" void kernel_launch(void* const* d_in, const int* in_sizes, int n_in,
                              void* d_out, int out_size) {
    const float* t    = (const float*)d_in[0];
    const float* y    = (const float*)d_in[1];
    const float* w1   = (const float*)d_in[2];
    const float* b1   = (const float*)d_in[3];
    const float* w2   = (const float*)d_in[4];
    const float* b2   = (const float*)d_in[5];
    const float* w3   = (const float*)d_in[6];
    const float* b3   = (const float*)d_in[7];
    const float* w4   = (const float*)d_in[8];
    const float* b4   = (const float*)d_in[9];
    const float* beta = (const float*)d_in[10];
    const float* gamma= (const float*)d_in[11];
    float* out = (float*)d_out;

    k_init<<<4, 256>>>(t, y, w1, b1, w2, b2, w3, b3, w4, b4, out);
    mega<<<NB, 256>>>(t, y, beta, gamma, out);
}

// round 8
// speedup vs baseline: 2.1385x; 1.0011x over previous
#include <cuda_runtime.h>
#include <math.h>

#define Tn 1024
#define Bn 512
#define CH 64
#define NCH 16
#define Hn 20
#define NB 128
#define OUT_DIFF (Tn * Bn * 3)

__device__ float g_cw[1024];   // cw[d] = me[Tn-d]*dt for d in [1,1023]; cw[0]=0

// ---------------- packed f32x2 helpers (sm_103a FFMA2 path) ----------------
__device__ __forceinline__ unsigned long long pk2(float lo, float hi) {
    unsigned long long r;
    asm("mov.b64 %0, {%1,%2};" : "=l"(r) : "f"(lo), "f"(hi));
    return r;
}
__device__ __forceinline__ void upk2(float& lo, float& hi, unsigned long long v) {
    asm("mov.b64 {%0,%1}, %2;" : "=f"(lo), "=f"(hi) : "l"(v));
}
__device__ __forceinline__ unsigned long long fma2(unsigned long long a,
                                                   unsigned long long b,
                                                   unsigned long long c) {
    unsigned long long d;
    asm("fma.rn.f32x2 %0, %1, %2, %3;" : "=l"(d) : "l"(a), "l"(b), "l"(c));
    return d;
}

// ============================================================
// k_init: MLP -> g_cw; solution row 0; diff row Tn-1 (zeros).
// ============================================================
__global__ void k_init(const float* __restrict__ t, const float* __restrict__ y,
                       const float* __restrict__ w1, const float* __restrict__ b1,
                       const float* __restrict__ w2, const float* __restrict__ b2,
                       const float* __restrict__ w3, const float* __restrict__ b3,
                       const float* __restrict__ w4, const float* __restrict__ b4,
                       float* __restrict__ out) {
    __shared__ float sw2[Hn * Hn], sw3[Hn * Hn];
    __shared__ float sw1[Hn], sb1[Hn], sb2[Hn], sb3[Hn], sw4[Hn];
    int tid = threadIdx.x;
    for (int i = tid; i < Hn * Hn; i += 256) { sw2[i] = w2[i]; sw3[i] = w3[i]; }
    if (tid < Hn) {
        sw1[tid] = w1[tid]; sb1[tid] = b1[tid];
        sb2[tid] = b2[tid]; sb3[tid] = b3[tid]; sw4[tid] = w4[tid];
    }
    __syncthreads();

    int r = blockIdx.x * 256 + tid;          // 0..1023
    float dt = t[0] - t[1];
    float tv = t[r];

    float h1[Hn], h2[Hn];
#pragma unroll
    for (int j = 0; j < Hn; j++) h1[j] = tanhf(tv * sw1[j] + sb1[j]);
#pragma unroll
    for (int j = 0; j < Hn; j++) {
        float a = sb2[j];
#pragma unroll
        for (int i = 0; i < Hn; i++) a += h1[i] * sw2[i * Hn + j];
        h2[j] = tanhf(a);
    }
#pragma unroll
    for (int j = 0; j < Hn; j++) {
        float a = sb3[j];
#pragma unroll
        for (int i = 0; i < Hn; i++) a += h2[i] * sw3[i * Hn + j];
        h1[j] = tanhf(a);
    }
    float a = b4[0];
#pragma unroll
    for (int i = 0; i < Hn; i++) a += h1[i] * sw4[i];
    float me = 1.0f / (1.0f + expf(-a));

    if (r > 0) g_cw[Tn - r] = me * dt;
    else       g_cw[0] = 0.0f;

    if (r < Bn) {
        float S0 = y[r * 3 + 0], I0 = y[r * 3 + 1], R0 = y[r * 3 + 2];
        float* so = out + (size_t)r * 3;
        so[0] = S0; so[1] = I0; so[2] = R0;
        float* df = out + OUT_DIFF + ((size_t)(Tn - 1) * Bn + r) * 3;
        df[0] = 0.0f; df[1] = 0.0f; df[2] = 0.0f;
    }
}

// ============================================================
// B serial steps for one chunk: 12-cyc recurrence, 4-ahead shfl,
// local window d<=4 via rolling registers, owner SEL saves.
// ============================================================
template <int FIRST>
__device__ __forceinline__ void stepsB(int k, int bb, int bj, int lane,
                                       float& S, float& I, float& Im2, float& Im3, float& Im4,
                                       float& bS, float tot,
                                       float acc0, float acc1,
                                       float dtv, float ngam, float betadt,
                                       float cw1, float cw2, float cw3, float cw4,
                                       const float* __restrict__ cwZ,
                                       float (*Ih)[Tn],
                                       float* __restrict__ out) {
    float svS0 = 0.f, svI0 = 0.f, svdS0 = 0.f, svdI0 = 0.f;
    float svS1, svI1, svdS1, svdI1;
    float preQ[4], preQ2[4];

    const int s0 = FIRST ? 1 : 0;
#pragma unroll
    for (int r = 0; r < 4; r++)
        preQ[(s0 + r) & 3] = __shfl_sync(0xffffffffu, acc0, s0 + r);

    // rest for first step: extracted + cw2*I[-2] + cw3*I[-3] + cw4*I[-4]
    float rest = preQ[s0 & 3];
    rest = fmaf(cw4, Im4, rest);
    rest = fmaf(cw3, Im3, rest);
    rest = fmaf(cw2, Im2, rest);

    // ---------- half 1: steps s0..31 ----------
#pragma unroll
    for (int s = 0; s < 32; s++) {
        if (FIRST && s == 0) continue;
        float integro = fmaf(cw1, I, rest);          // chain: +4 after I
        float bSI = bS * I;                          // +4
        if (s + 4 < 32) preQ[(s + 4) & 3]   = __shfl_sync(0xffffffffu, acc0, s + 4);
        else            preQ2[(s - 28) & 3] = __shfl_sync(0xffffffffu, acc1, s - 28);
        float dI = fmaf(ngam, I, bSI);               // +8
        float dS = integro - bSI;                    // +8
        float Inew = fmaf(dtv, dI, I);               // +12  <- period
        S  = fmaf(dtv, dS, S);
        bS = fmaf(betadt, dS, bS);                   // +12, ready for next bSI
        bool own = (lane == s);
        svS0  = own ? S    : svS0;
        svI0  = own ? Inew : svI0;
        svdS0 = own ? dS   : svdS0;
        svdI0 = own ? dI   : svdI0;
        acc0 = fmaf(cwZ[32 + lane - s], Inew, acc0); // d<=4 zeroed in cwZ
        acc1 = fmaf(cwZ[64 + lane - s], Inew, acc1);
        float pn = (s + 1 < 32) ? preQ[(s + 1) & 3] : preQ2[0];
        rest = pn;
        rest = fmaf(cw4, Im3, rest);                 // I[s-3] -> d=4 at step s+1
        rest = fmaf(cw3, Im2, rest);
        rest = fmaf(cw2, I, rest);
        Im4 = Im3; Im3 = Im2; Im2 = I; I = Inew;
    }

    // ---------- half 2: steps 32..63 ----------
#pragma unroll
    for (int s2 = 0; s2 < 32; s2++) {
        float integro = fmaf(cw1, I, rest);
        float bSI = bS * I;
        if (s2 + 4 < 32) preQ2[(s2 + 4) & 3] = __shfl_sync(0xffffffffu, acc1, s2 + 4);
        float dI = fmaf(ngam, I, bSI);
        float dS = integro - bSI;
        float Inew = fmaf(dtv, dI, I);
        S  = fmaf(dtv, dS, S);
        bS = fmaf(betadt, dS, bS);
        bool own = (lane == s2);
        svS1  = own ? S    : svS1;
        svI1  = own ? Inew : svI1;
        svdS1 = own ? dS   : svdS1;
        svdI1 = own ? dI   : svdI1;
        acc1 = fmaf(cwZ[32 + lane - s2], Inew, acc1);
        rest = preQ2[(s2 + 1) & 3];                  // dead at s2=31 (rebuilt next chunk)
        rest = fmaf(cw4, Im3, rest);
        rest = fmaf(cw3, Im2, rest);
        rest = fmaf(cw2, I, rest);
        Im4 = Im3; Im3 = Im2; Im2 = I; I = Inew;
    }

    // ---------- flush (off the serial path) ----------
    float* const diffb = out + OUT_DIFF;
    int j0 = k * CH + lane;
    if (!(FIRST && lane == 0)) {
        float* so = out + ((size_t)j0 * Bn + bb) * 3;
        so[0] = svS0; so[1] = svI0; so[2] = tot - svS0 - svI0;
        float* df = diffb + ((size_t)(j0 - 1) * Bn + bb) * 3;
        df[0] = svdS0; df[1] = svdI0; df[2] = -svdS0 - svdI0;
        Ih[bj][j0] = svI0;
    }
    int j1 = j0 + 32;
    {
        float* so = out + ((size_t)j1 * Bn + bb) * 3;
        so[0] = svS1; so[1] = svI1; so[2] = tot - svS1 - svI1;
        float* df = diffb + ((size_t)(j1 - 1) * Bn + bb) * 3;
        df[0] = svdS1; df[1] = svdI1; df[2] = -svdS1 - svdI1;
        Ih[bj][j1] = svI1;
    }
}

// ============================================================
// mega: persistent block-local solver. 128 blocks x 256 thr.
// Warps 4-7: B (HIGH arbiter priority). Warps 0-3: A (f32x2 conv).
// ============================================================
__global__ void __launch_bounds__(256, 1)
mega(const float* __restrict__ t, const float* __restrict__ y,
     const float* __restrict__ beta_p, const float* __restrict__ gamma_p,
     float* __restrict__ out) {
    __shared__ float cwZ[1056];        // cwZ[i]=0 for i<=36 (pad + d<=4); else cw[i-32]
    __shared__ float Ih[4][Tn];        // block-local I history
    __shared__ float baseS[2][4][CH];  // A partials, parity double-buffered

    const int tid  = threadIdx.x;
    const int blk  = blockIdx.x;
    const int wid  = tid >> 5;
    const int lane = tid & 31;
    const bool isB = (wid >= 4);
    const int bj   = isB ? (wid - 4) : wid;
    const int bb   = blk * 4 + bj;

    for (int i = tid; i < 1056; i += 256)
        cwZ[i] = (i <= 36) ? 0.0f : g_cw[i - 32];
    if (tid < 4) Ih[tid][0] = y[(blk * 4 + tid) * 3 + 1];
    __syncthreads();

    const float dtv   = t[0] - t[1];
    const float beta  = beta_p[0];
    const float gamma = gamma_p[0];
    const float ngam  = -gamma;
    const float betadt = beta * dtv;
    const float cw1 = __ldg(&g_cw[1]), cw2 = __ldg(&g_cw[2]);
    const float cw3 = __ldg(&g_cw[3]), cw4 = __ldg(&g_cw[4]);

    // persistent B state (wid 4-7)
    float S = 0.f, I = 0.f, tot = 0.f, bS = 0.f;
    float Im2 = 0.f, Im3 = 0.f, Im4 = 0.f;
    if (isB) {
        S = y[bb * 3 + 0]; I = y[bb * 3 + 1];
        tot = S + I + y[bb * 3 + 2];
        bS  = beta * S;
    }

    for (int k = 0; k < NCH; k++) {
        if (isB) {
            // ---------- seed accumulators ----------
            float acc0, acc1;
            if (k >= 2) { acc0 = baseS[k & 1][bj][lane]; acc1 = baseS[k & 1][bj][lane + 32]; }
            else        { acc0 = 0.f; acc1 = 0.f; }
            if (k >= 1) {
                // recent chunk, 4 partial accumulators each (short chains)
                const float* Iprev = &Ih[bj][(k - 1) * CH];
                const float* c0 = &cwZ[96 + lane];     // d = 64+lane-m (d<=4 zeroed)
                const float* c1 = &cwZ[128 + lane];    // d = 96+lane-m
                float a00 = 0.f, a01 = 0.f, a02 = 0.f, a03 = 0.f;
                float a10 = 0.f, a11 = 0.f, a12 = 0.f, a13 = 0.f;
#pragma unroll 4
                for (int m = 0; m < CH; m += 4) {
                    float v0 = Iprev[m + 0], v1 = Iprev[m + 1];
                    float v2 = Iprev[m + 2], v3 = Iprev[m + 3];
                    a00 = fmaf(c0[-(m + 0)], v0, a00);
                    a01 = fmaf(c0[-(m + 1)], v1, a01);
                    a02 = fmaf(c0[-(m + 2)], v2, a02);
                    a03 = fmaf(c0[-(m + 3)], v3, a03);
                    a10 = fmaf(c1[-(m + 0)], v0, a10);
                    a11 = fmaf(c1[-(m + 1)], v1, a11);
                    a12 = fmaf(c1[-(m + 2)], v2, a12);
                    a13 = fmaf(c1[-(m + 3)], v3, a13);
                }
                acc0 += (a00 + a01) + (a02 + a03);
                acc1 += (a10 + a11) + (a12 + a13);
                stepsB<0>(k, bb, bj, lane, S, I, Im2, Im3, Im4, bS, tot, acc0, acc1,
                          dtv, ngam, betadt, cw1, cw2, cw3, cw4, cwZ, Ih, out);
            } else {
                acc0 = cwZ[32 + lane] * I;             // I_0 scatter (d<=4 zeroed)
                acc1 = cwZ[64 + lane] * I;
                stepsB<1>(k, bb, bj, lane, S, I, Im2, Im3, Im4, bS, tot, acc0, acc1,
                          dtv, ngam, betadt, cw1, cw2, cw3, cw4, cwZ, Ih, out);
            }
        } else if (k >= 1 && k <= NCH - 2) {
            // ---------- A: history partials for chunk K=k+1, m < 64k ----------
            // lane j8 owns 8 consecutive targets; packed (r, r+4) f32x2 FIFO.
            const int K    = k + 1;
            const int j8   = lane & 7;
            const int g    = lane >> 3;
            const int M    = CH * k;
            const int mlen = M >> 2;
            const int m0   = g * mlen;
            const int m1   = m0 + mlen;
            const int Cc   = 32 + CH * K + 8 * j8;
            const float* Ihp = Ih[bj];

            float q0 = cwZ[Cc + 0 - m0], q1 = cwZ[Cc + 1 - m0];
            float q2 = cwZ[Cc + 2 - m0], q3 = cwZ[Cc + 3 - m0];
            float q4 = cwZ[Cc + 4 - m0], q5 = cwZ[Cc + 5 - m0];
            float q6 = cwZ[Cc + 6 - m0], q7 = cwZ[Cc + 7 - m0];
            unsigned long long P0 = pk2(q0, q4), P1 = pk2(q1, q5);
            unsigned long long P2 = pk2(q2, q6), P3 = pk2(q3, q7);
            unsigned long long A0 = pk2(0.f, 0.f), A1 = A0, A2 = A0, A3 = A0;

#pragma unroll 4
            for (int m = m0; m < m1; m++) {
                float Iv = Ihp[m];
                unsigned long long Iv2 = pk2(Iv, Iv);
                A0 = fma2(P0, Iv2, A0);
                A1 = fma2(P1, Iv2, A1);
                A2 = fma2(P2, Iv2, A2);
                A3 = fma2(P3, Iv2, A3);
                float nc = cwZ[Cc - 1 - m];            // coef r=0 at m+1
                float lo3, hi3; upk2(lo3, hi3, P3);    // lo3 = q[3]
                P3 = P2; P2 = P1; P1 = P0;
                P0 = pk2(nc, lo3);                     // (q'[0], q'[4]) = (nc, q[3])
            }

            float acc[8];
            upk2(acc[0], acc[4], A0);
            upk2(acc[1], acc[5], A1);
            upk2(acc[2], acc[6], A2);
            upk2(acc[3], acc[7], A3);
#pragma unroll
            for (int r = 0; r < 8; r++) {
                acc[r] += __shfl_xor_sync(0xffffffffu, acc[r], 8);
                acc[r] += __shfl_xor_sync(0xffffffffu, acc[r], 16);
            }
            if (lane < 8) {
                float4* dst = (float4*)&baseS[K & 1][bj][8 * j8];
                dst[0] = make_float4(acc[0], acc[1], acc[2], acc[3]);
                dst[1] = make_float4(acc[4], acc[5], acc[6], acc[7]);
            }
        }
        __syncthreads();
    }
}

// ================= launch: 2 graph nodes =================
extern "C" void kernel_launch(void* const* d_in, const int* in_sizes, int n_in,
                              void* d_out, int out_size) {
    const float* t    = (const float*)d_in[0];
    const float* y    = (const float*)d_in[1];
    const float* w1   = (const float*)d_in[2];
    const float* b1   = (const float*)d_in[3];
    const float* w2   = (const float*)d_in[4];
    const float* b2   = (const float*)d_in[5];
    const float* w3   = (const float*)d_in[6];
    const float* b3   = (const float*)d_in[7];
    const float* w4   = (const float*)d_in[8];
    const float* b4   = (const float*)d_in[9];
    const float* beta = (const float*)d_in[10];
    const float* gamma= (const float*)d_in[11];
    float* out = (float*)d_out;

    k_init<<<4, 256>>>(t, y, w1, b1, w2, b2, w3, b3, w4, b4, out);
    mega<<<NB, 256>>>(t, y, beta, gamma, out);
}

// round 10
// speedup vs baseline: 2.6978x; 1.2616x over previous
#include <cuda_runtime.h>
#include <math.h>

#define Tn 1024
#define Bn 512
#define CH 64
#define NCH 16
#define Hn 20
#define NB 128
#define OUT_DIFF (Tn * Bn * 3)

__device__ float g_cw[1024];   // cw[d] = me[Tn-d]*dt for d in [1,1023]; cw[0]=0

// ---------------- packed f32x2 helpers ----------------
__device__ __forceinline__ unsigned long long pk2(float lo, float hi) {
    unsigned long long r;
    asm("mov.b64 %0, {%1,%2};" : "=l"(r) : "f"(lo), "f"(hi));
    return r;
}
__device__ __forceinline__ void upk2(float& lo, float& hi, unsigned long long v) {
    asm("mov.b64 {%0,%1}, %2;" : "=f"(lo), "=f"(hi) : "l"(v));
}
__device__ __forceinline__ unsigned long long fma2(unsigned long long a,
                                                   unsigned long long b,
                                                   unsigned long long c) {
    unsigned long long d;
    asm("fma.rn.f32x2 %0, %1, %2, %3;" : "=l"(d) : "l"(a), "l"(b), "l"(c));
    return d;
}

// ============================================================
// k_init: MLP -> g_cw; solution row 0; diff row Tn-1 (zeros).
// ============================================================
__global__ void k_init(const float* __restrict__ t, const float* __restrict__ y,
                       const float* __restrict__ w1, const float* __restrict__ b1,
                       const float* __restrict__ w2, const float* __restrict__ b2,
                       const float* __restrict__ w3, const float* __restrict__ b3,
                       const float* __restrict__ w4, const float* __restrict__ b4,
                       float* __restrict__ out) {
    __shared__ float sw2[Hn * Hn], sw3[Hn * Hn];
    __shared__ float sw1[Hn], sb1[Hn], sb2[Hn], sb3[Hn], sw4[Hn];
    int tid = threadIdx.x;
    for (int i = tid; i < Hn * Hn; i += 256) { sw2[i] = w2[i]; sw3[i] = w3[i]; }
    if (tid < Hn) {
        sw1[tid] = w1[tid]; sb1[tid] = b1[tid];
        sb2[tid] = b2[tid]; sb3[tid] = b3[tid]; sw4[tid] = w4[tid];
    }
    __syncthreads();

    int r = blockIdx.x * 256 + tid;
    float dt = t[0] - t[1];
    float tv = t[r];

    float h1[Hn], h2[Hn];
#pragma unroll
    for (int j = 0; j < Hn; j++) h1[j] = tanhf(tv * sw1[j] + sb1[j]);
#pragma unroll
    for (int j = 0; j < Hn; j++) {
        float a = sb2[j];
#pragma unroll
        for (int i = 0; i < Hn; i++) a += h1[i] * sw2[i * Hn + j];
        h2[j] = tanhf(a);
    }
#pragma unroll
    for (int j = 0; j < Hn; j++) {
        float a = sb3[j];
#pragma unroll
        for (int i = 0; i < Hn; i++) a += h2[i] * sw3[i * Hn + j];
        h1[j] = tanhf(a);
    }
    float a = b4[0];
#pragma unroll
    for (int i = 0; i < Hn; i++) a += h1[i] * sw4[i];
    float me = 1.0f / (1.0f + expf(-a));

    if (r > 0) g_cw[Tn - r] = me * dt;
    else       g_cw[0] = 0.0f;

    if (r < Bn) {
        float S0 = y[r * 3 + 0], I0 = y[r * 3 + 1], R0 = y[r * 3 + 2];
        float* so = out + (size_t)r * 3;
        so[0] = S0; so[1] = I0; so[2] = R0;
        float* df = out + OUT_DIFF + ((size_t)(Tn - 1) * Bn + r) * 3;
        df[0] = 0.0f; df[1] = 0.0f; df[2] = 0.0f;
    }
}

// ============================================================
// B serial steps (unchanged from R8): 12-cyc recurrence, 4-ahead shfl.
// ============================================================
template <int FIRST>
__device__ __forceinline__ void stepsB(int k, int bb, int bj, int lane,
                                       float& S, float& I, float& Im2, float& Im3, float& Im4,
                                       float& bS, float tot,
                                       float acc0, float acc1,
                                       float dtv, float ngam, float betadt,
                                       float cw1, float cw2, float cw3, float cw4,
                                       const float* __restrict__ cwZ,
                                       float (*Ih)[Tn],
                                       float* __restrict__ out) {
    float svS0 = 0.f, svI0 = 0.f, svdS0 = 0.f, svdI0 = 0.f;
    float svS1, svI1, svdS1, svdI1;
    float preQ[4], preQ2[4];

    const int s0 = FIRST ? 1 : 0;
#pragma unroll
    for (int r = 0; r < 4; r++)
        preQ[(s0 + r) & 3] = __shfl_sync(0xffffffffu, acc0, s0 + r);

    float rest = preQ[s0 & 3];
    rest = fmaf(cw4, Im4, rest);
    rest = fmaf(cw3, Im3, rest);
    rest = fmaf(cw2, Im2, rest);

#pragma unroll
    for (int s = 0; s < 32; s++) {
        if (FIRST && s == 0) continue;
        float integro = fmaf(cw1, I, rest);
        float bSI = bS * I;
        if (s + 4 < 32) preQ[(s + 4) & 3]   = __shfl_sync(0xffffffffu, acc0, s + 4);
        else            preQ2[(s - 28) & 3] = __shfl_sync(0xffffffffu, acc1, s - 28);
        float dI = fmaf(ngam, I, bSI);
        float dS = integro - bSI;
        float Inew = fmaf(dtv, dI, I);
        S  = fmaf(dtv, dS, S);
        bS = fmaf(betadt, dS, bS);
        bool own = (lane == s);
        svS0  = own ? S    : svS0;
        svI0  = own ? Inew : svI0;
        svdS0 = own ? dS   : svdS0;
        svdI0 = own ? dI   : svdI0;
        acc0 = fmaf(cwZ[32 + lane - s], Inew, acc0);
        acc1 = fmaf(cwZ[64 + lane - s], Inew, acc1);
        float pn = (s + 1 < 32) ? preQ[(s + 1) & 3] : preQ2[0];
        rest = pn;
        rest = fmaf(cw4, Im3, rest);
        rest = fmaf(cw3, Im2, rest);
        rest = fmaf(cw2, I, rest);
        Im4 = Im3; Im3 = Im2; Im2 = I; I = Inew;
    }

#pragma unroll
    for (int s2 = 0; s2 < 32; s2++) {
        float integro = fmaf(cw1, I, rest);
        float bSI = bS * I;
        if (s2 + 4 < 32) preQ2[(s2 + 4) & 3] = __shfl_sync(0xffffffffu, acc1, s2 + 4);
        float dI = fmaf(ngam, I, bSI);
        float dS = integro - bSI;
        float Inew = fmaf(dtv, dI, I);
        S  = fmaf(dtv, dS, S);
        bS = fmaf(betadt, dS, bS);
        bool own = (lane == s2);
        svS1  = own ? S    : svS1;
        svI1  = own ? Inew : svI1;
        svdS1 = own ? dS   : svdS1;
        svdI1 = own ? dI   : svdI1;
        acc1 = fmaf(cwZ[32 + lane - s2], Inew, acc1);
        rest = preQ2[(s2 + 1) & 3];
        rest = fmaf(cw4, Im3, rest);
        rest = fmaf(cw3, Im2, rest);
        rest = fmaf(cw2, I, rest);
        Im4 = Im3; Im3 = Im2; Im2 = I; I = Inew;
    }

    float* const diffb = out + OUT_DIFF;
    int j0 = k * CH + lane;
    if (!(FIRST && lane == 0)) {
        float* so = out + ((size_t)j0 * Bn + bb) * 3;
        so[0] = svS0; so[1] = svI0; so[2] = tot - svS0 - svI0;
        float* df = diffb + ((size_t)(j0 - 1) * Bn + bb) * 3;
        df[0] = svdS0; df[1] = svdI0; df[2] = -svdS0 - svdI0;
        Ih[bj][j0] = svI0;
    }
    int j1 = j0 + 32;
    {
        float* so = out + ((size_t)j1 * Bn + bb) * 3;
        so[0] = svS1; so[1] = svI1; so[2] = tot - svS1 - svI1;
        float* df = diffb + ((size_t)(j1 - 1) * Bn + bb) * 3;
        df[0] = svdS1; df[1] = svdI1; df[2] = -svdS1 - svdI1;
        Ih[bj][j1] = svI1;
    }
}

// ============================================================
// mega: persistent block-local solver. Warps 4-7: B. Warps 0-3: A.
// A inner loop: vectorized LDS (float4 Iv broadcast + float4 coef refill).
// ============================================================
__global__ void __launch_bounds__(256, 1)
mega(const float* __restrict__ t, const float* __restrict__ y,
     const float* __restrict__ beta_p, const float* __restrict__ gamma_p,
     float* __restrict__ out) {
    __shared__ __align__(16) float cwZ[1056];   // 0 for i<=36; else cw[i-32]
    __shared__ __align__(16) float Ih[4][Tn];   // block-local I history
    __shared__ float baseS[2][4][CH];           // A partials, parity double-buffered

    const int tid  = threadIdx.x;
    const int blk  = blockIdx.x;
    const int wid  = tid >> 5;
    const int lane = tid & 31;
    const bool isB = (wid >= 4);
    const int bj   = isB ? (wid - 4) : wid;
    const int bb   = blk * 4 + bj;

    for (int i = tid; i < 1056; i += 256)
        cwZ[i] = (i <= 36) ? 0.0f : g_cw[i - 32];
    if (tid < 4) Ih[tid][0] = y[(blk * 4 + tid) * 3 + 1];
    __syncthreads();

    const float dtv    = t[0] - t[1];
    const float beta   = beta_p[0];
    const float gamma  = gamma_p[0];
    const float ngam   = -gamma;
    const float betadt = beta * dtv;
    const float cw1 = __ldg(&g_cw[1]), cw2 = __ldg(&g_cw[2]);
    const float cw3 = __ldg(&g_cw[3]), cw4 = __ldg(&g_cw[4]);

    float S = 0.f, I = 0.f, tot = 0.f, bS = 0.f;
    float Im2 = 0.f, Im3 = 0.f, Im4 = 0.f;
    if (isB) {
        S = y[bb * 3 + 0]; I = y[bb * 3 + 1];
        tot = S + I + y[bb * 3 + 2];
        bS  = beta * S;
    }

    for (int k = 0; k < NCH; k++) {
        if (isB) {
            // ---------- seed accumulators ----------
            float acc0, acc1;
            if (k >= 2) { acc0 = baseS[k & 1][bj][lane]; acc1 = baseS[k & 1][bj][lane + 32]; }
            else        { acc0 = 0.f; acc1 = 0.f; }
            if (k >= 1) {
                // recent chunk: float4-broadcast Iv, scalar conflict-free coefs
                const float4* Ip4 = (const float4*)&Ih[bj][(k - 1) * CH];
                const float* c0 = &cwZ[96 + lane];
                const float* c1 = &cwZ[128 + lane];
                float a00 = 0.f, a01 = 0.f, a02 = 0.f, a03 = 0.f;
                float a10 = 0.f, a11 = 0.f, a12 = 0.f, a13 = 0.f;
#pragma unroll 4
                for (int q = 0; q < 16; q++) {
                    float4 v = Ip4[q];
                    int m = q * 4;
                    a00 = fmaf(c0[-(m + 0)], v.x, a00);
                    a01 = fmaf(c0[-(m + 1)], v.y, a01);
                    a02 = fmaf(c0[-(m + 2)], v.z, a02);
                    a03 = fmaf(c0[-(m + 3)], v.w, a03);
                    a10 = fmaf(c1[-(m + 0)], v.x, a10);
                    a11 = fmaf(c1[-(m + 1)], v.y, a11);
                    a12 = fmaf(c1[-(m + 2)], v.z, a12);
                    a13 = fmaf(c1[-(m + 3)], v.w, a13);
                }
                acc0 += (a00 + a01) + (a02 + a03);
                acc1 += (a10 + a11) + (a12 + a13);
                stepsB<0>(k, bb, bj, lane, S, I, Im2, Im3, Im4, bS, tot, acc0, acc1,
                          dtv, ngam, betadt, cw1, cw2, cw3, cw4, cwZ, Ih, out);
            } else {
                acc0 = cwZ[32 + lane] * I;
                acc1 = cwZ[64 + lane] * I;
                stepsB<1>(k, bb, bj, lane, S, I, Im2, Im3, Im4, bS, tot, acc0, acc1,
                          dtv, ngam, betadt, cw1, cw2, cw3, cw4, cwZ, Ih, out);
            }
        } else if (k >= 1 && k <= NCH - 2) {
            // ---------- A: history partials for chunk K=k+1, m < 64k ----------
            // lane j8 owns 8 consecutive targets; (r, r+4) f32x2 FIFO;
            // vectorized loads: float4 Iv broadcast + float4 coef refill per 4 m.
            const int K    = k + 1;
            const int j8   = lane & 7;
            const int g    = lane >> 3;
            const int M    = CH * k;
            const int mlen = M >> 2;               // multiple of 16
            const int m0   = g * mlen;
            const int Cc   = 32 + CH * K + 8 * j8; // multiple of 4
            const float* Ihp = Ih[bj];

            float q0 = cwZ[Cc + 0 - m0], q1 = cwZ[Cc + 1 - m0];
            float q2 = cwZ[Cc + 2 - m0], q3 = cwZ[Cc + 3 - m0];
            float q4 = cwZ[Cc + 4 - m0], q5 = cwZ[Cc + 5 - m0];
            float q6 = cwZ[Cc + 6 - m0], q7 = cwZ[Cc + 7 - m0];
            unsigned long long P0 = pk2(q0, q4), P1 = pk2(q1, q5);
            unsigned long long P2 = pk2(q2, q6), P3 = pk2(q3, q7);
            unsigned long long A0 = pk2(0.f, 0.f), A1 = A0, A2 = A0, A3 = A0;

#pragma unroll 2
            for (int m = m0; m < m0 + mlen; m += 4) {
                float4 Iv4 = *(const float4*)(Ihp + m);            // broadcast
                float4 F   = *(const float4*)(&cwZ[Cc - 4 - m]);   // nc(m..m+3)=F.w,z,y,x
                unsigned long long Iv2;
                float lo, hi;

                Iv2 = pk2(Iv4.x, Iv4.x);
                A0 = fma2(P0, Iv2, A0); A1 = fma2(P1, Iv2, A1);
                A2 = fma2(P2, Iv2, A2); A3 = fma2(P3, Iv2, A3);
                upk2(lo, hi, P3); unsigned long long N0 = pk2(F.w, lo);

                Iv2 = pk2(Iv4.y, Iv4.y);
                A0 = fma2(N0, Iv2, A0); A1 = fma2(P0, Iv2, A1);
                A2 = fma2(P1, Iv2, A2); A3 = fma2(P2, Iv2, A3);
                upk2(lo, hi, P2); unsigned long long N1 = pk2(F.z, lo);

                Iv2 = pk2(Iv4.z, Iv4.z);
                A0 = fma2(N1, Iv2, A0); A1 = fma2(N0, Iv2, A1);
                A2 = fma2(P0, Iv2, A2); A3 = fma2(P1, Iv2, A3);
                upk2(lo, hi, P1); unsigned long long N2 = pk2(F.y, lo);

                Iv2 = pk2(Iv4.w, Iv4.w);
                A0 = fma2(N2, Iv2, A0); A1 = fma2(N1, Iv2, A1);
                A2 = fma2(N0, Iv2, A2); A3 = fma2(P0, Iv2, A3);
                upk2(lo, hi, P0); unsigned long long N3 = pk2(F.x, lo);

                P0 = N3; P1 = N2; P2 = N1; P3 = N0;
            }

            float acc[8];
            upk2(acc[0], acc[4], A0);
            upk2(acc[1], acc[5], A1);
            upk2(acc[2], acc[6], A2);
            upk2(acc[3], acc[7], A3);
#pragma unroll
            for (int r = 0; r < 8; r++) {
                acc[r] += __shfl_xor_sync(0xffffffffu, acc[r], 8);
                acc[r] += __shfl_xor_sync(0xffffffffu, acc[r], 16);
            }
            if (lane < 8) {
                float4* dst = (float4*)&baseS[K & 1][bj][8 * j8];
                dst[0] = make_float4(acc[0], acc[1], acc[2], acc[3]);
                dst[1] = make_float4(acc[4], acc[5], acc[6], acc[7]);
            }
        }
        __syncthreads();
    }
}

// ================= launch: 2 graph nodes =================
extern "C" void kernel_launch(void* const* d_in, const int* in_sizes, int n_in,
                              void* d_out, int out_size) {
    const float* t    = (const float*)d_in[0];
    const float* y    = (const float*)d_in[1];
    const float* w1   = (const float*)d_in[2];
    const float* b1   = (const float*)d_in[3];
    const float* w2   = (const float*)d_in[4];
    const float* b2   = (const float*)d_in[5];
    const float* w3   = (const float*)d_in[6];
    const float* b3   = (const float*)d_in[7];
    const float* w4   = (const float*)d_in[8];
    const float* b4   = (const float*)d_in[9];
    const float* beta = (const float*)d_in[10];
    const float* gamma= (const float*)d_in[11];
    float* out = (float*)d_out;

    k_init<<<4, 256>>>(t, y, w1, b1, w2, b2, w3, b3, w4, b4, out);
    mega<<<NB, 256>>>(t, y, beta, gamma, out);
}